// round 15
// baseline (speedup 1.0000x reference)
#include <cuda_runtime.h>
#include <cuda_fp16.h>
#include <stdint.h>

#define DIM     1024
#define HEADS   8
#define DH      64
#define NSEQ    4096
#define BATCH   2
#define TOKENS  (BATCH*NSEQ)     // 8192
#define QKV_N   (3*HEADS*DH)     // 1536
#define AO_N    (HEADS*DH)       // 512
#define BH_N    (BATCH*HEADS)    // 16
#define QSCALE  0.18033688011112042f   // 0.125 * log2(e)
#define HONES   0x3C003C00u             // half2(1.0, 1.0)

// ===================== scratch globals (fp16, hi only) =======================
__device__ __align__(16) __half g_xn[TOKENS * DIM];
__device__ __align__(16) __half g_wq[QKV_N * DIM];      // K-major
__device__ __align__(16) __half g_wo[DIM * AO_N];       // K-major
__device__ __align__(16) __half g_q [BH_N * NSEQ * DH]; // log2-scaled
__device__ __align__(16) __half g_k [BH_N * NSEQ * DH];
__device__ __align__(16) __half g_v [BH_N * NSEQ * DH];
__device__ __align__(16) __half g_ao[TOKENS * AO_N];

// ===================== PTX helpers ===========================================
__device__ __forceinline__ uint32_t smem_u32(const void* p) {
    uint32_t a;
    asm("{ .reg .u64 t; cvta.to.shared.u64 t, %1; cvt.u32.u64 %0, t; }"
        : "=r"(a) : "l"(p));
    return a;
}
__device__ __forceinline__ void cp16(uint32_t dst, const void* src) {
    asm volatile("cp.async.cg.shared.global [%0], [%1], 16;"
                 :: "r"(dst), "l"(src));
}
#define CP_COMMIT() asm volatile("cp.async.commit_group;" ::: "memory")
#define CP_WAIT1()  asm volatile("cp.async.wait_group 1;"  ::: "memory")

__device__ __forceinline__ void ldsm4(uint32_t (&r)[4], uint32_t a) {
    asm volatile("ldmatrix.sync.aligned.m8n8.x4.shared.b16 {%0,%1,%2,%3}, [%4];"
        : "=r"(r[0]), "=r"(r[1]), "=r"(r[2]), "=r"(r[3]) : "r"(a));
}
__device__ __forceinline__ void ldsm4t(uint32_t (&r)[4], uint32_t a) {
    asm volatile("ldmatrix.sync.aligned.m8n8.x4.trans.shared.b16 {%0,%1,%2,%3}, [%4];"
        : "=r"(r[0]), "=r"(r[1]), "=r"(r[2]), "=r"(r[3]) : "r"(a));
}
__device__ __forceinline__ void mma16816(float (&d)[4], const uint32_t (&a)[4],
                                         uint32_t b0, uint32_t b1) {
    asm volatile(
        "mma.sync.aligned.m16n8k16.row.col.f32.f16.f16.f32 "
        "{%0,%1,%2,%3}, {%4,%5,%6,%7}, {%8,%9}, {%0,%1,%2,%3};"
        : "+f"(d[0]), "+f"(d[1]), "+f"(d[2]), "+f"(d[3])
        : "r"(a[0]), "r"(a[1]), "r"(a[2]), "r"(a[3]), "r"(b0), "r"(b1));
}
__device__ __forceinline__ float ex2(float x) {
    float y;
    asm("ex2.approx.f32 %0, %1;" : "=f"(y) : "f"(x));
    return y;
}
// pack (x0,x1) to f16x2 then 2^x elementwise (P fragment builder)
__device__ __forceinline__ uint32_t exp2_pack(float x0, float x1) {
    uint32_t u, r;
    asm("cvt.rn.f16x2.f32 %0, %1, %2;" : "=r"(u) : "f"(x1), "f"(x0));
    asm("ex2.approx.f16x2 %0, %1;" : "=r"(r) : "r"(u));
    return r;
}
__device__ __forceinline__ void pack2h(float x0, float x1, uint32_t& ph) {
    asm("cvt.rn.f16x2.f32 %0, %1, %2;" : "=r"(ph) : "f"(x1), "f"(x0));
}
__device__ __forceinline__ uint32_t sw128(int r, int cb) {
    return (uint32_t)(r * 128 + ((((cb >> 4) ^ (r & 7))) << 4));
}

// ===================== 1) fused prep: LN + weight converts (fp16) ============
#define CONV0_BLKS ((QKV_N / 32) * (DIM / 32))   // 1536
#define CONV1_BLKS ((DIM / 32) * (AO_N / 32))    // 512
__global__ void prep_kernel(const float* __restrict__ x,
                            const float* __restrict__ gamma,
                            const float* __restrict__ beta,
                            const float* __restrict__ wqkv,
                            const float* __restrict__ wout) {
    const int blk = blockIdx.x;
    const int tid = threadIdx.x;
    if (blk < TOKENS) {
        const int t = blk;
        const float4 v = *(const float4*)(x + (size_t)t * DIM + tid * 4);
        float s  = v.x + v.y + v.z + v.w;
        float s2 = v.x*v.x + v.y*v.y + v.z*v.z + v.w*v.w;
        #pragma unroll
        for (int o = 16; o > 0; o >>= 1) {
            s  += __shfl_down_sync(0xffffffffu, s,  o);
            s2 += __shfl_down_sync(0xffffffffu, s2, o);
        }
        __shared__ float ws[8], ws2[8];
        __shared__ float s_mu, s_rstd;
        const int wid = tid >> 5, lane = tid & 31;
        if (lane == 0) { ws[wid] = s; ws2[wid] = s2; }
        __syncthreads();
        if (tid == 0) {
            float S = 0.f, S2 = 0.f;
            #pragma unroll
            for (int i = 0; i < 8; i++) { S += ws[i]; S2 += ws2[i]; }
            float mu  = S * (1.0f / DIM);
            float var = S2 * (1.0f / DIM) - mu * mu;
            s_mu = mu;
            s_rstd = rsqrtf(var + 1e-5f);
        }
        __syncthreads();
        const float mu = s_mu, rstd = s_rstd;
        const float4 g = *(const float4*)(gamma + tid * 4);
        const float4 b = *(const float4*)(beta  + tid * 4);
        uint32_t h0, h1;
        pack2h((v.x - mu) * rstd * g.x + b.x, (v.y - mu) * rstd * g.y + b.y, h0);
        pack2h((v.z - mu) * rstd * g.z + b.z, (v.w - mu) * rstd * g.w + b.w, h1);
        const size_t o = (size_t)t * DIM + tid * 4;
        *(uint32_t*)(g_xn + o)     = h0;
        *(uint32_t*)(g_xn + o + 2) = h1;
    } else {
        __shared__ float tbuf[32][33];
        int idx, Kd, Nd;
        const float* src;
        __half* hi;
        if (blk < TOKENS + CONV0_BLKS) {
            idx = blk - TOKENS; Kd = DIM; Nd = QKV_N;
            src = wqkv; hi = g_wq;
        } else {
            idx = blk - TOKENS - CONV0_BLKS; Kd = AO_N; Nd = DIM;
            src = wout; hi = g_wo;
        }
        const int nb = Nd / 32;
        const int n0 = (idx % nb) * 32, k0 = (idx / nb) * 32;
        const int tx = tid & 31, ty = tid >> 5;
        #pragma unroll
        for (int i = ty; i < 32; i += 8)
            tbuf[i][tx] = src[(size_t)(k0 + i) * Nd + n0 + tx];
        __syncthreads();
        #pragma unroll
        for (int i = ty; i < 32; i += 8)
            hi[(size_t)(n0 + i) * Kd + k0 + tx] = __float2half_rn(tbuf[tx][i]);
    }
}

// ===================== 2) GEMM: 1-term fp16, 128x128, Kc=64, 3-stage =========
#define GSTAGE 32768
__device__ __forceinline__ void gemm_load(uint32_t sb, int st,
    const __half* __restrict__ A, const __half* __restrict__ B,
    int m0, int n0, int K, int k0, int tid)
{
    const uint32_t base = sb + st * GSTAGE;
    #pragma unroll
    for (int t = 0; t < 8; t++) {
        const int rc = tid + (t & 3) * 128;          // 0..511
        const int r  = rc >> 2;                      // 0..127
        const int ch = (rc & 3) + (t >> 2) * 4;      // 0..7
        const uint32_t dA = base + sw128(r, ch * 16);
        const uint32_t dB = base + 16384 + sw128(r, ch * 16);
        cp16(dA, A + (size_t)(m0 + r) * K + k0 + ch * 8);
        cp16(dB, B + (size_t)(n0 + r) * K + k0 + ch * 8);
    }
}

template<int MODE>
__global__ void __launch_bounds__(128, 2) gemm_mma(float* __restrict__ Cout) {
    constexpr int K  = (MODE == 0) ? DIM : AO_N;
    constexpr int NC = K / 64;
    extern __shared__ char dsm[];
    const uint32_t sb = smem_u32(dsm);

    const int tid = threadIdx.x, lane = tid & 31, warp = tid >> 5;
    const int g = lane >> 2, tig = lane & 3;
    const int wm = (warp >> 1) * 64, wn = (warp & 1) * 64;
    const int m0 = blockIdx.y * 128, n0 = blockIdx.x * 128;

    const __half* __restrict__ A = (MODE == 0) ? g_xn : g_ao;
    const __half* __restrict__ B = (MODE == 0) ? g_wq : g_wo;

    float c[4][8][4] = {};

    gemm_load(sb, 0, A, B, m0, n0, K, 0,  tid);
    CP_COMMIT();
    gemm_load(sb, 1, A, B, m0, n0, K, 64, tid);
    CP_COMMIT();

    int stc = 0, stp = 2;
    for (int cc = 0; cc < NC; cc++) {
        CP_WAIT1();
        __syncthreads();
        if (cc + 2 < NC)
            gemm_load(sb, stp, A, B, m0, n0, K, (cc + 2) * 64, tid);
        CP_COMMIT();

        const uint32_t uA = sb + stc * GSTAGE;
        const uint32_t uB = uA + 16384;

        #pragma unroll
        for (int kk = 0; kk < 4; kk++) {
            const int acb = kk * 32 + (lane >> 4) * 16;
            uint32_t ah[4][4];
            #pragma unroll
            for (int i = 0; i < 4; i++) {
                const int row = wm + i * 16 + (lane & 15);
                ldsm4(ah[i], uA + sw128(row, acb));
            }
            #pragma unroll
            for (int nb = 0; nb < 4; nb++) {
                const int row = wn + nb * 16 + (lane & 7) + ((lane >> 3) & 1) * 8;
                uint32_t bh[4];
                ldsm4(bh, uB + sw128(row, acb));
                #pragma unroll
                for (int i = 0; i < 4; i++) {
                    mma16816(c[i][nb*2+0], ah[i], bh[0], bh[2]);
                    mma16816(c[i][nb*2+1], ah[i], bh[1], bh[3]);
                }
            }
        }
        stc = (stc == 2) ? 0 : stc + 1;
        stp = (stp == 2) ? 0 : stp + 1;
    }

    if (MODE == 0) {
        #pragma unroll
        for (int i = 0; i < 4; i++) {
            const int r0g = m0 + wm + i * 16 + g;
            #pragma unroll
            for (int j = 0; j < 8; j++) {
                const int col  = n0 + wn + j * 8 + tig * 2;
                const int part = col >> 9;
                const int hd   = (col >> 6) & 7;
                const int d    = col & 63;
                __half* dst = (part == 0) ? g_q : ((part == 1) ? g_k : g_v);
                const float sc = (part == 0) ? QSCALE : 1.0f;
                #pragma unroll
                for (int rr = 0; rr < 2; rr++) {
                    const int row = r0g + rr * 8;
                    const int bb = row >> 12, seq = row & 4095;
                    const size_t off = (((size_t)(bb * HEADS + hd)) * NSEQ + seq) * DH + d;
                    uint32_t ph;
                    pack2h(c[i][j][rr*2+0] * sc, c[i][j][rr*2+1] * sc, ph);
                    *(uint32_t*)(dst + off) = ph;
                }
            }
        }
    } else {
        #pragma unroll
        for (int i = 0; i < 4; i++) {
            const int r0g = m0 + wm + i * 16 + g;
            #pragma unroll
            for (int j = 0; j < 8; j++) {
                const int col = n0 + wn + j * 8 + tig * 2;
                #pragma unroll
                for (int rr = 0; rr < 2; rr++) {
                    const int row = r0g + rr * 8;
                    *(float2*)(Cout + (size_t)row * DIM + col) =
                        make_float2(c[i][j][rr*2+0], c[i][j][rr*2+1]);
                }
            }
        }
    }
}

// ===================== 3) flash attention: occ 3, f16x2 exp, ones-MMA l ======
// smem: Q @0 (16KB persistent), stages @16384: 3 x 16KB (K@0, V@8192).
// Total 65536 B/CTA; 3 CTAs/SM = 192KB.
#define AST   16384
#define AQOFF 16384
__device__ __forceinline__ void kv_load(uint32_t sb, int st, size_t kvbase,
                                        int kt, int tid) {
    const int r  = tid >> 1;
    const int c0 = (tid & 1) * 4;
    const uint32_t base = sb + AQOFF + st * AST;
    #pragma unroll
    for (int it = 0; it < 4; it++) {
        const int ch = c0 + it;
        const uint32_t d = base + sw128(r, ch * 16);
        const size_t src = kvbase + (size_t)(kt * 64 + r) * DH + ch * 8;
        cp16(d,        g_k + src);
        cp16(d + 8192, g_v + src);
    }
}

__global__ void __launch_bounds__(128, 3) attn_kernel() {
    extern __shared__ char dsm[];
    const uint32_t sb = smem_u32(dsm);
    const int qt = (int)gridDim.x - 1 - (int)blockIdx.x;  // big tiles first
    const int bh = blockIdx.y, b = bh >> 3, h = bh & 7;
    const int tid = threadIdx.x, lane = tid & 31, warp = tid >> 5;
    const int g = lane >> 2, tig = lane & 3;
    const int wm = warp * 32;
    const size_t kvbase = (size_t)bh * NSEQ * DH;

    // ---- stage Q (persistent @0) ----
    const size_t qbase = ((size_t)bh * NSEQ + qt * 128) * DH;
    for (int i = tid; i < 1024; i += 128) {
        const int r = i >> 3, cch = i & 7;
        *(uint4*)(dsm + sw128(r, cch * 16)) =
            *(const uint4*)(g_q + qbase + (size_t)r * DH + cch * 8);
    }

    const int ktmax = 2 * qt + 1;
    kv_load(sb, 0, kvbase, 0, tid);
    CP_COMMIT();
    kv_load(sb, 1, kvbase, 1, tid);
    CP_COMMIT();
    __syncthreads();                         // Q visible to all warps

    float o[2][8][4] = {};
    float mv[4] = {-1e30f, -1e30f, -1e30f, -1e30f};
    float lv[4] = {0.f, 0.f, 0.f, 0.f};

    int stc = 0, stp = 2;
    for (int kt = 0; kt <= ktmax; kt++) {
        CP_WAIT1();
        __syncthreads();
        if (kt + 2 <= ktmax)
            kv_load(sb, stp, kvbase, kt + 2, tid);
        CP_COMMIT();

        const uint32_t uK = sb + AQOFF + stc * AST;
        const uint32_t uV = uK + 8192;

        // ---- S = Q K^T (1-term fp16), Q frags reloaded from smem ----
        float s[2][8][4] = {};
        #pragma unroll
        for (int kk = 0; kk < 4; kk++) {
            const int cb = kk * 32 + (lane >> 4) * 16;
            uint32_t q0[4], q1[4];
            ldsm4(q0, sb + sw128(wm      + (lane & 15), cb));
            ldsm4(q1, sb + sw128(wm + 16 + (lane & 15), cb));
            #pragma unroll
            for (int np = 0; np < 2; np++) {
                const int nb0 = np * 2, nb1 = np * 2 + 1;
                const int r0 = nb0 * 16 + (lane & 7) + ((lane >> 3) & 1) * 8;
                const int r1 = nb1 * 16 + (lane & 7) + ((lane >> 3) & 1) * 8;
                uint32_t kh0[4], kh1[4];
                ldsm4(kh0, uK + sw128(r0, cb));
                ldsm4(kh1, uK + sw128(r1, cb));
                mma16816(s[0][nb0*2+0], q0, kh0[0], kh0[2]);
                mma16816(s[0][nb0*2+1], q0, kh0[1], kh0[3]);
                mma16816(s[0][nb1*2+0], q0, kh1[0], kh1[2]);
                mma16816(s[0][nb1*2+1], q0, kh1[1], kh1[3]);
                mma16816(s[1][nb0*2+0], q1, kh0[0], kh0[2]);
                mma16816(s[1][nb0*2+1], q1, kh0[1], kh0[3]);
                mma16816(s[1][nb1*2+0], q1, kh1[0], kh1[2]);
                mma16816(s[1][nb1*2+1], q1, kh1[1], kh1[3]);
            }
        }
        // ---- causal mask (diagonal tiles only) ----
        if (kt >= 2 * qt) {
            #pragma unroll
            for (int mf = 0; mf < 2; mf++) {
                const int row0 = qt * 128 + wm + mf * 16 + g;
                #pragma unroll
                for (int j = 0; j < 8; j++) {
                    const int col = kt * 64 + j * 8 + tig * 2;
                    if (col     > row0)     s[mf][j][0] = -1e30f;
                    if (col + 1 > row0)     s[mf][j][1] = -1e30f;
                    if (col     > row0 + 8) s[mf][j][2] = -1e30f;
                    if (col + 1 > row0 + 8) s[mf][j][3] = -1e30f;
                }
            }
        }
        // ---- row max ----
        float mx[4] = {-1e30f, -1e30f, -1e30f, -1e30f};
        #pragma unroll
        for (int mf = 0; mf < 2; mf++)
            #pragma unroll
            for (int j = 0; j < 8; j++) {
                mx[mf*2+0] = fmaxf(mx[mf*2+0], fmaxf(s[mf][j][0], s[mf][j][1]));
                mx[mf*2+1] = fmaxf(mx[mf*2+1], fmaxf(s[mf][j][2], s[mf][j][3]));
            }
        #pragma unroll
        for (int i = 0; i < 4; i++) {
            mx[i] = fmaxf(mx[i], __shfl_xor_sync(0xffffffffu, mx[i], 1));
            mx[i] = fmaxf(mx[i], __shfl_xor_sync(0xffffffffu, mx[i], 2));
        }
        if (mx[0] > mv[0] || mx[1] > mv[1] || mx[2] > mv[2] || mx[3] > mv[3]) {
            float cor[4];
            #pragma unroll
            for (int i = 0; i < 4; i++) {
                const float mn = fmaxf(mv[i], mx[i]);
                cor[i] = ex2(mv[i] - mn);
                lv[i] *= cor[i];
                mv[i] = mn;
            }
            #pragma unroll
            for (int mf = 0; mf < 2; mf++)
                #pragma unroll
                for (int j = 0; j < 8; j++) {
                    o[mf][j][0] *= cor[mf*2+0]; o[mf][j][1] *= cor[mf*2+0];
                    o[mf][j][2] *= cor[mf*2+1]; o[mf][j][3] *= cor[mf*2+1];
                }
        }
        // ---- exp (f16x2) + PV + ones-MMA row sums ----
        float lsum[2][4] = {};
        #pragma unroll
        for (int kk = 0; kk < 4; kk++) {
            const int r = kk * 16 + (lane & 7) + ((lane >> 4) << 3);
            uint32_t pah[2][4];
            #pragma unroll
            for (int mf = 0; mf < 2; mf++) {
                pah[mf][0] = exp2_pack(s[mf][2*kk  ][0] - mv[mf*2+0],
                                       s[mf][2*kk  ][1] - mv[mf*2+0]);
                pah[mf][1] = exp2_pack(s[mf][2*kk  ][2] - mv[mf*2+1],
                                       s[mf][2*kk  ][3] - mv[mf*2+1]);
                pah[mf][2] = exp2_pack(s[mf][2*kk+1][0] - mv[mf*2+0],
                                       s[mf][2*kk+1][1] - mv[mf*2+0]);
                pah[mf][3] = exp2_pack(s[mf][2*kk+1][2] - mv[mf*2+1],
                                       s[mf][2*kk+1][3] - mv[mf*2+1]);
                mma16816(lsum[mf], pah[mf], HONES, HONES);
            }
            #pragma unroll
            for (int half = 0; half < 2; half++) {
                uint32_t vh0[4], vh1[4];
                const int nb0 = half * 2, nb1 = half * 2 + 1;
                const int cb0 = nb0 * 32 + ((lane >> 3) & 1) * 16;
                const int cb1 = nb1 * 32 + ((lane >> 3) & 1) * 16;
                ldsm4t(vh0, uV + sw128(r, cb0));
                ldsm4t(vh1, uV + sw128(r, cb1));
                #pragma unroll
                for (int mf = 0; mf < 2; mf++) {
                    mma16816(o[mf][nb0*2+0], pah[mf], vh0[0], vh0[2]);
                    mma16816(o[mf][nb0*2+1], pah[mf], vh0[1], vh0[3]);
                    mma16816(o[mf][nb1*2+0], pah[mf], vh1[0], vh1[2]);
                    mma16816(o[mf][nb1*2+1], pah[mf], vh1[1], vh1[3]);
                }
            }
        }
        lv[0] += lsum[0][0];
        lv[1] += lsum[0][2];
        lv[2] += lsum[1][0];
        lv[3] += lsum[1][2];

        stc = (stc == 2) ? 0 : stc + 1;
        stp = (stp == 2) ? 0 : stp + 1;
    }

    // ---- epilogue ----
    float inv[4];
    #pragma unroll
    for (int i = 0; i < 4; i++) inv[i] = 1.0f / (lv[i] + 1e-10f);
    #pragma unroll
    for (int mf = 0; mf < 2; mf++) {
        const int row0 = qt * 128 + wm + mf * 16 + g;
        #pragma unroll
        for (int j = 0; j < 8; j++) {
            const int col = h * DH + j * 8 + tig * 2;
            {
                const size_t off = (size_t)(b * NSEQ + row0) * AO_N + col;
                uint32_t ph;
                pack2h(o[mf][j][0] * inv[mf*2+0], o[mf][j][1] * inv[mf*2+0], ph);
                *(uint32_t*)(g_ao + off) = ph;
            }
            {
                const size_t off = (size_t)(b * NSEQ + row0 + 8) * AO_N + col;
                uint32_t ph;
                pack2h(o[mf][j][2] * inv[mf*2+1], o[mf][j][3] * inv[mf*2+1], ph);
                *(uint32_t*)(g_ao + off) = ph;
            }
        }
    }
}

// ===================== launch ================================================
extern "C" void kernel_launch(void* const* d_in, const int* in_sizes, int n_in,
                              void* d_out, int out_size) {
    const float* x     = (const float*)d_in[0];
    const float* gamma = (const float*)d_in[1];
    const float* beta  = (const float*)d_in[2];
    const float* wqkv  = (const float*)d_in[3];
    const float* wout  = (const float*)d_in[4];
    float* out = (float*)d_out;

    cudaFuncSetAttribute(gemm_mma<0>, cudaFuncAttributeMaxDynamicSharedMemorySize, 3 * GSTAGE);
    cudaFuncSetAttribute(gemm_mma<1>, cudaFuncAttributeMaxDynamicSharedMemorySize, 3 * GSTAGE);
    cudaFuncSetAttribute(attn_kernel, cudaFuncAttributeMaxDynamicSharedMemorySize, AQOFF + 3 * AST);

    prep_kernel<<<TOKENS + CONV0_BLKS + CONV1_BLKS, 256>>>(x, gamma, beta, wqkv, wout);
    gemm_mma<0><<<dim3(QKV_N / 128, TOKENS / 128), 128, 3 * GSTAGE>>>(nullptr);
    attn_kernel<<<dim3(NSEQ / 128, BH_N), 128, AQOFF + 3 * AST>>>();
    gemm_mma<1><<<dim3(DIM / 128, TOKENS / 128), 128, 3 * GSTAGE>>>(out);
}

// round 16
// speedup vs baseline: 1.5481x; 1.5481x over previous
#include <cuda_runtime.h>
#include <cuda_fp16.h>
#include <stdint.h>

#define DIM     1024
#define HEADS   8
#define DH      64
#define NSEQ    4096
#define BATCH   2
#define TOKENS  (BATCH*NSEQ)     // 8192
#define QKV_N   (3*HEADS*DH)     // 1536
#define AO_N    (HEADS*DH)       // 512
#define BH_N    (BATCH*HEADS)    // 16
#define QSCALE  0.18033688011112042f   // 0.125 * log2(e)
#define HONES   0x3C003C00u             // half2(1.0, 1.0)

// ===================== scratch globals (fp16, hi only) =======================
__device__ __align__(16) __half g_xn[TOKENS * DIM];
__device__ __align__(16) __half g_wq[QKV_N * DIM];      // K-major
__device__ __align__(16) __half g_wo[DIM * AO_N];       // K-major
__device__ __align__(16) __half g_q [BH_N * NSEQ * DH]; // log2-scaled
__device__ __align__(16) __half g_k [BH_N * NSEQ * DH];
__device__ __align__(16) __half g_v [BH_N * NSEQ * DH];
__device__ __align__(16) __half g_ao[TOKENS * AO_N];

// ===================== PTX helpers ===========================================
__device__ __forceinline__ uint32_t smem_u32(const void* p) {
    uint32_t a;
    asm("{ .reg .u64 t; cvta.to.shared.u64 t, %1; cvt.u32.u64 %0, t; }"
        : "=r"(a) : "l"(p));
    return a;
}
__device__ __forceinline__ void cp16(uint32_t dst, const void* src) {
    asm volatile("cp.async.cg.shared.global [%0], [%1], 16;"
                 :: "r"(dst), "l"(src));
}
#define CP_COMMIT() asm volatile("cp.async.commit_group;" ::: "memory")
#define CP_WAIT1()  asm volatile("cp.async.wait_group 1;"  ::: "memory")

__device__ __forceinline__ void ldsm4(uint32_t (&r)[4], uint32_t a) {
    asm volatile("ldmatrix.sync.aligned.m8n8.x4.shared.b16 {%0,%1,%2,%3}, [%4];"
        : "=r"(r[0]), "=r"(r[1]), "=r"(r[2]), "=r"(r[3]) : "r"(a));
}
__device__ __forceinline__ void ldsm4t(uint32_t (&r)[4], uint32_t a) {
    asm volatile("ldmatrix.sync.aligned.m8n8.x4.trans.shared.b16 {%0,%1,%2,%3}, [%4];"
        : "=r"(r[0]), "=r"(r[1]), "=r"(r[2]), "=r"(r[3]) : "r"(a));
}
__device__ __forceinline__ void mma16816(float (&d)[4], const uint32_t (&a)[4],
                                         uint32_t b0, uint32_t b1) {
    asm volatile(
        "mma.sync.aligned.m16n8k16.row.col.f32.f16.f16.f32 "
        "{%0,%1,%2,%3}, {%4,%5,%6,%7}, {%8,%9}, {%0,%1,%2,%3};"
        : "+f"(d[0]), "+f"(d[1]), "+f"(d[2]), "+f"(d[3])
        : "r"(a[0]), "r"(a[1]), "r"(a[2]), "r"(a[3]), "r"(b0), "r"(b1));
}
__device__ __forceinline__ float ex2(float x) {
    float y;
    asm("ex2.approx.f32 %0, %1;" : "=f"(y) : "f"(x));
    return y;
}
// pack (x0,x1) to f16x2 then 2^x elementwise (P fragment builder)
__device__ __forceinline__ uint32_t exp2_pack(float x0, float x1) {
    uint32_t u, r;
    asm("cvt.rn.f16x2.f32 %0, %1, %2;" : "=r"(u) : "f"(x1), "f"(x0));
    asm("ex2.approx.f16x2 %0, %1;" : "=r"(r) : "r"(u));
    return r;
}
__device__ __forceinline__ void pack2h(float x0, float x1, uint32_t& ph) {
    asm("cvt.rn.f16x2.f32 %0, %1, %2;" : "=r"(ph) : "f"(x1), "f"(x0));
}
__device__ __forceinline__ uint32_t sw128(int r, int cb) {
    return (uint32_t)(r * 128 + ((((cb >> 4) ^ (r & 7))) << 4));
}

// ===================== 1) fused prep: LN + weight converts (fp16) ============
#define CONV0_BLKS ((QKV_N / 32) * (DIM / 32))   // 1536
#define CONV1_BLKS ((DIM / 32) * (AO_N / 32))    // 512
__global__ void prep_kernel(const float* __restrict__ x,
                            const float* __restrict__ gamma,
                            const float* __restrict__ beta,
                            const float* __restrict__ wqkv,
                            const float* __restrict__ wout) {
    const int blk = blockIdx.x;
    const int tid = threadIdx.x;
    if (blk < TOKENS) {
        const int t = blk;
        const float4 v = *(const float4*)(x + (size_t)t * DIM + tid * 4);
        float s  = v.x + v.y + v.z + v.w;
        float s2 = v.x*v.x + v.y*v.y + v.z*v.z + v.w*v.w;
        #pragma unroll
        for (int o = 16; o > 0; o >>= 1) {
            s  += __shfl_down_sync(0xffffffffu, s,  o);
            s2 += __shfl_down_sync(0xffffffffu, s2, o);
        }
        __shared__ float ws[8], ws2[8];
        __shared__ float s_mu, s_rstd;
        const int wid = tid >> 5, lane = tid & 31;
        if (lane == 0) { ws[wid] = s; ws2[wid] = s2; }
        __syncthreads();
        if (tid == 0) {
            float S = 0.f, S2 = 0.f;
            #pragma unroll
            for (int i = 0; i < 8; i++) { S += ws[i]; S2 += ws2[i]; }
            float mu  = S * (1.0f / DIM);
            float var = S2 * (1.0f / DIM) - mu * mu;
            s_mu = mu;
            s_rstd = rsqrtf(var + 1e-5f);
        }
        __syncthreads();
        const float mu = s_mu, rstd = s_rstd;
        const float4 g = *(const float4*)(gamma + tid * 4);
        const float4 b = *(const float4*)(beta  + tid * 4);
        uint32_t h0, h1;
        pack2h((v.x - mu) * rstd * g.x + b.x, (v.y - mu) * rstd * g.y + b.y, h0);
        pack2h((v.z - mu) * rstd * g.z + b.z, (v.w - mu) * rstd * g.w + b.w, h1);
        const size_t o = (size_t)t * DIM + tid * 4;
        *(uint32_t*)(g_xn + o)     = h0;
        *(uint32_t*)(g_xn + o + 2) = h1;
    } else {
        __shared__ float tbuf[32][33];
        int idx, Kd, Nd;
        const float* src;
        __half* hi;
        if (blk < TOKENS + CONV0_BLKS) {
            idx = blk - TOKENS; Kd = DIM; Nd = QKV_N;
            src = wqkv; hi = g_wq;
        } else {
            idx = blk - TOKENS - CONV0_BLKS; Kd = AO_N; Nd = DIM;
            src = wout; hi = g_wo;
        }
        const int nb = Nd / 32;
        const int n0 = (idx % nb) * 32, k0 = (idx / nb) * 32;
        const int tx = tid & 31, ty = tid >> 5;
        #pragma unroll
        for (int i = ty; i < 32; i += 8)
            tbuf[i][tx] = src[(size_t)(k0 + i) * Nd + n0 + tx];
        __syncthreads();
        #pragma unroll
        for (int i = ty; i < 32; i += 8)
            hi[(size_t)(n0 + i) * Kd + k0 + tx] = __float2half_rn(tbuf[tx][i]);
    }
}

// ===================== 2) GEMM: 1-term fp16, 128x128, Kc=64, 3-stage =========
#define GSTAGE 32768
__device__ __forceinline__ void gemm_load(uint32_t sb, int st,
    const __half* __restrict__ A, const __half* __restrict__ B,
    int m0, int n0, int K, int k0, int tid)
{
    const uint32_t base = sb + st * GSTAGE;
    #pragma unroll
    for (int t = 0; t < 8; t++) {
        const int rc = tid + (t & 3) * 128;          // 0..511
        const int r  = rc >> 2;                      // 0..127
        const int ch = (rc & 3) + (t >> 2) * 4;      // 0..7
        const uint32_t dA = base + sw128(r, ch * 16);
        const uint32_t dB = base + 16384 + sw128(r, ch * 16);
        cp16(dA, A + (size_t)(m0 + r) * K + k0 + ch * 8);
        cp16(dB, B + (size_t)(n0 + r) * K + k0 + ch * 8);
    }
}

template<int MODE>
__global__ void __launch_bounds__(128, 2) gemm_mma(float* __restrict__ Cout) {
    constexpr int K  = (MODE == 0) ? DIM : AO_N;
    constexpr int NC = K / 64;
    extern __shared__ char dsm[];
    const uint32_t sb = smem_u32(dsm);

    const int tid = threadIdx.x, lane = tid & 31, warp = tid >> 5;
    const int g = lane >> 2, tig = lane & 3;
    const int wm = (warp >> 1) * 64, wn = (warp & 1) * 64;
    const int m0 = blockIdx.y * 128, n0 = blockIdx.x * 128;

    const __half* __restrict__ A = (MODE == 0) ? g_xn : g_ao;
    const __half* __restrict__ B = (MODE == 0) ? g_wq : g_wo;

    float c[4][8][4] = {};

    gemm_load(sb, 0, A, B, m0, n0, K, 0,  tid);
    CP_COMMIT();
    gemm_load(sb, 1, A, B, m0, n0, K, 64, tid);
    CP_COMMIT();

    int stc = 0, stp = 2;
    for (int cc = 0; cc < NC; cc++) {
        CP_WAIT1();
        __syncthreads();
        if (cc + 2 < NC)
            gemm_load(sb, stp, A, B, m0, n0, K, (cc + 2) * 64, tid);
        CP_COMMIT();

        const uint32_t uA = sb + stc * GSTAGE;
        const uint32_t uB = uA + 16384;

        #pragma unroll
        for (int kk = 0; kk < 4; kk++) {
            const int acb = kk * 32 + (lane >> 4) * 16;
            uint32_t ah[4][4];
            #pragma unroll
            for (int i = 0; i < 4; i++) {
                const int row = wm + i * 16 + (lane & 15);
                ldsm4(ah[i], uA + sw128(row, acb));
            }
            #pragma unroll
            for (int nb = 0; nb < 4; nb++) {
                const int row = wn + nb * 16 + (lane & 7) + ((lane >> 3) & 1) * 8;
                uint32_t bh[4];
                ldsm4(bh, uB + sw128(row, acb));
                #pragma unroll
                for (int i = 0; i < 4; i++) {
                    mma16816(c[i][nb*2+0], ah[i], bh[0], bh[2]);
                    mma16816(c[i][nb*2+1], ah[i], bh[1], bh[3]);
                }
            }
        }
        stc = (stc == 2) ? 0 : stc + 1;
        stp = (stp == 2) ? 0 : stp + 1;
    }

    if (MODE == 0) {
        #pragma unroll
        for (int i = 0; i < 4; i++) {
            const int r0g = m0 + wm + i * 16 + g;
            #pragma unroll
            for (int j = 0; j < 8; j++) {
                const int col  = n0 + wn + j * 8 + tig * 2;
                const int part = col >> 9;
                const int hd   = (col >> 6) & 7;
                const int d    = col & 63;
                __half* dst = (part == 0) ? g_q : ((part == 1) ? g_k : g_v);
                const float sc = (part == 0) ? QSCALE : 1.0f;
                #pragma unroll
                for (int rr = 0; rr < 2; rr++) {
                    const int row = r0g + rr * 8;
                    const int bb = row >> 12, seq = row & 4095;
                    const size_t off = (((size_t)(bb * HEADS + hd)) * NSEQ + seq) * DH + d;
                    uint32_t ph;
                    pack2h(c[i][j][rr*2+0] * sc, c[i][j][rr*2+1] * sc, ph);
                    *(uint32_t*)(dst + off) = ph;
                }
            }
        }
    } else {
        #pragma unroll
        for (int i = 0; i < 4; i++) {
            const int r0g = m0 + wm + i * 16 + g;
            #pragma unroll
            for (int j = 0; j < 8; j++) {
                const int col = n0 + wn + j * 8 + tig * 2;
                #pragma unroll
                for (int rr = 0; rr < 2; rr++) {
                    const int row = r0g + rr * 8;
                    *(float2*)(Cout + (size_t)row * DIM + col) =
                        make_float2(c[i][j][rr*2+0], c[i][j][rr*2+1]);
                }
            }
        }
    }
}

// ===================== 3) flash attention: R14 structure + f16x2 exp =========
// stage (16384 B): K @0 (64x64 halves), V @8192. 3 stages = 48KB, occ 2.
// Q (16KB) staged in stage-1 area during prologue; Q frags persistent in regs.
#define AST 16384
__device__ __forceinline__ void kv_load(uint32_t sb, int st, size_t kvbase,
                                        int kt, int tid) {
    const int r  = tid >> 1;                // 0..63
    const int c0 = (tid & 1) * 4;
    const uint32_t base = sb + st * AST;
    #pragma unroll
    for (int it = 0; it < 4; it++) {
        const int ch = c0 + it;
        const uint32_t d = base + sw128(r, ch * 16);
        const size_t src = kvbase + (size_t)(kt * 64 + r) * DH + ch * 8;
        cp16(d,        g_k + src);
        cp16(d + 8192, g_v + src);
    }
}

__global__ void __launch_bounds__(128, 2) attn_kernel() {
    extern __shared__ char dsm[];
    const uint32_t sb = smem_u32(dsm);
    const int qt = (int)gridDim.x - 1 - (int)blockIdx.x;  // big tiles first
    const int bh = blockIdx.y, b = bh >> 3, h = bh & 7;
    const int tid = threadIdx.x, lane = tid & 31, warp = tid >> 5;
    const int g = lane >> 2, tig = lane & 3;
    const int wm = warp * 32;
    const size_t kvbase = (size_t)bh * NSEQ * DH;

    // ---- stage Q into stage-1 area (@16384) ----
    const size_t qbase = ((size_t)bh * NSEQ + qt * 128) * DH;
    for (int i = tid; i < 1024; i += 128) {
        const int r = i >> 3, cch = i & 7;
        *(uint4*)(dsm + 16384 + sw128(r, cch * 16)) =
            *(const uint4*)(g_q + qbase + (size_t)r * DH + cch * 8);
    }
    __syncthreads();
    uint32_t qh[2][4][4];
    #pragma unroll
    for (int mf = 0; mf < 2; mf++)
        #pragma unroll
        for (int kk = 0; kk < 4; kk++) {
            const int r  = wm + mf * 16 + (lane & 15);
            const int cb = kk * 32 + (lane >> 4) * 16;
            ldsm4(qh[mf][kk], sb + 16384 + sw128(r, cb));
        }
    __syncthreads();

    const int ktmax = 2 * qt + 1;
    kv_load(sb, 0, kvbase, 0, tid);
    CP_COMMIT();
    kv_load(sb, 1, kvbase, 1, tid);
    CP_COMMIT();

    float o[2][8][4] = {};
    float mv[4] = {-1e30f, -1e30f, -1e30f, -1e30f};
    float lv[4] = {0.f, 0.f, 0.f, 0.f};

    int stc = 0, stp = 2;
    for (int kt = 0; kt <= ktmax; kt++) {
        CP_WAIT1();
        __syncthreads();
        if (kt + 2 <= ktmax)
            kv_load(sb, stp, kvbase, kt + 2, tid);
        CP_COMMIT();

        const uint32_t uK = sb + stc * AST;
        const uint32_t uV = uK + 8192;

        // ---- S = Q K^T (1-term fp16), log2 domain ----
        float s[2][8][4] = {};
        #pragma unroll
        for (int kk = 0; kk < 4; kk++) {
            const int cb = kk * 32 + (lane >> 4) * 16;
            #pragma unroll
            for (int np = 0; np < 2; np++) {
                const int nb0 = np * 2, nb1 = np * 2 + 1;
                const int r0 = nb0 * 16 + (lane & 7) + ((lane >> 3) & 1) * 8;
                const int r1 = nb1 * 16 + (lane & 7) + ((lane >> 3) & 1) * 8;
                uint32_t kh0[4], kh1[4];
                ldsm4(kh0, uK + sw128(r0, cb));
                ldsm4(kh1, uK + sw128(r1, cb));
                #pragma unroll
                for (int mf = 0; mf < 2; mf++) {
                    mma16816(s[mf][nb0*2+0], qh[mf][kk], kh0[0], kh0[2]);
                    mma16816(s[mf][nb0*2+1], qh[mf][kk], kh0[1], kh0[3]);
                    mma16816(s[mf][nb1*2+0], qh[mf][kk], kh1[0], kh1[2]);
                    mma16816(s[mf][nb1*2+1], qh[mf][kk], kh1[1], kh1[3]);
                }
            }
        }
        // ---- causal mask (diagonal tiles only) ----
        if (kt >= 2 * qt) {
            #pragma unroll
            for (int mf = 0; mf < 2; mf++) {
                const int row0 = qt * 128 + wm + mf * 16 + g;
                #pragma unroll
                for (int j = 0; j < 8; j++) {
                    const int col = kt * 64 + j * 8 + tig * 2;
                    if (col     > row0)     s[mf][j][0] = -1e30f;
                    if (col + 1 > row0)     s[mf][j][1] = -1e30f;
                    if (col     > row0 + 8) s[mf][j][2] = -1e30f;
                    if (col + 1 > row0 + 8) s[mf][j][3] = -1e30f;
                }
            }
        }
        // ---- row max ----
        float mx[4] = {-1e30f, -1e30f, -1e30f, -1e30f};
        #pragma unroll
        for (int mf = 0; mf < 2; mf++)
            #pragma unroll
            for (int j = 0; j < 8; j++) {
                mx[mf*2+0] = fmaxf(mx[mf*2+0], fmaxf(s[mf][j][0], s[mf][j][1]));
                mx[mf*2+1] = fmaxf(mx[mf*2+1], fmaxf(s[mf][j][2], s[mf][j][3]));
            }
        #pragma unroll
        for (int i = 0; i < 4; i++) {
            mx[i] = fmaxf(mx[i], __shfl_xor_sync(0xffffffffu, mx[i], 1));
            mx[i] = fmaxf(mx[i], __shfl_xor_sync(0xffffffffu, mx[i], 2));
        }
        if (mx[0] > mv[0] || mx[1] > mv[1] || mx[2] > mv[2] || mx[3] > mv[3]) {
            float cor[4];
            #pragma unroll
            for (int i = 0; i < 4; i++) {
                const float mn = fmaxf(mv[i], mx[i]);
                cor[i] = ex2(mv[i] - mn);
                lv[i] *= cor[i];
                mv[i] = mn;
            }
            #pragma unroll
            for (int mf = 0; mf < 2; mf++)
                #pragma unroll
                for (int j = 0; j < 8; j++) {
                    o[mf][j][0] *= cor[mf*2+0]; o[mf][j][1] *= cor[mf*2+0];
                    o[mf][j][2] *= cor[mf*2+1]; o[mf][j][3] *= cor[mf*2+1];
                }
        }
        // ---- exp (f16x2 fused) + PV + ones-MMA row sums ----
        float lsum[2][4] = {};
        #pragma unroll
        for (int kk = 0; kk < 4; kk++) {
            const int r = kk * 16 + (lane & 7) + ((lane >> 4) << 3);
            uint32_t pah[2][4];
            #pragma unroll
            for (int mf = 0; mf < 2; mf++) {
                pah[mf][0] = exp2_pack(s[mf][2*kk  ][0] - mv[mf*2+0],
                                       s[mf][2*kk  ][1] - mv[mf*2+0]);
                pah[mf][1] = exp2_pack(s[mf][2*kk  ][2] - mv[mf*2+1],
                                       s[mf][2*kk  ][3] - mv[mf*2+1]);
                pah[mf][2] = exp2_pack(s[mf][2*kk+1][0] - mv[mf*2+0],
                                       s[mf][2*kk+1][1] - mv[mf*2+0]);
                pah[mf][3] = exp2_pack(s[mf][2*kk+1][2] - mv[mf*2+1],
                                       s[mf][2*kk+1][3] - mv[mf*2+1]);
                mma16816(lsum[mf], pah[mf], HONES, HONES);
            }
            #pragma unroll
            for (int half = 0; half < 2; half++) {
                uint32_t vh0[4], vh1[4];
                const int nb0 = half * 2, nb1 = half * 2 + 1;
                const int cb0 = nb0 * 32 + ((lane >> 3) & 1) * 16;
                const int cb1 = nb1 * 32 + ((lane >> 3) & 1) * 16;
                ldsm4t(vh0, uV + sw128(r, cb0));
                ldsm4t(vh1, uV + sw128(r, cb1));
                #pragma unroll
                for (int mf = 0; mf < 2; mf++) {
                    mma16816(o[mf][nb0*2+0], pah[mf], vh0[0], vh0[2]);
                    mma16816(o[mf][nb0*2+1], pah[mf], vh0[1], vh0[3]);
                    mma16816(o[mf][nb1*2+0], pah[mf], vh1[0], vh1[2]);
                    mma16816(o[mf][nb1*2+1], pah[mf], vh1[1], vh1[3]);
                }
            }
        }
        lv[0] += lsum[0][0];
        lv[1] += lsum[0][2];
        lv[2] += lsum[1][0];
        lv[3] += lsum[1][2];

        stc = (stc == 2) ? 0 : stc + 1;
        stp = (stp == 2) ? 0 : stp + 1;
    }

    // ---- epilogue ----
    float inv[4];
    #pragma unroll
    for (int i = 0; i < 4; i++) inv[i] = 1.0f / (lv[i] + 1e-10f);
    #pragma unroll
    for (int mf = 0; mf < 2; mf++) {
        const int row0 = qt * 128 + wm + mf * 16 + g;
        #pragma unroll
        for (int j = 0; j < 8; j++) {
            const int col = h * DH + j * 8 + tig * 2;
            {
                const size_t off = (size_t)(b * NSEQ + row0) * AO_N + col;
                uint32_t ph;
                pack2h(o[mf][j][0] * inv[mf*2+0], o[mf][j][1] * inv[mf*2+0], ph);
                *(uint32_t*)(g_ao + off) = ph;
            }
            {
                const size_t off = (size_t)(b * NSEQ + row0 + 8) * AO_N + col;
                uint32_t ph;
                pack2h(o[mf][j][2] * inv[mf*2+1], o[mf][j][3] * inv[mf*2+1], ph);
                *(uint32_t*)(g_ao + off) = ph;
            }
        }
    }
}

// ===================== launch ================================================
extern "C" void kernel_launch(void* const* d_in, const int* in_sizes, int n_in,
                              void* d_out, int out_size) {
    const float* x     = (const float*)d_in[0];
    const float* gamma = (const float*)d_in[1];
    const float* beta  = (const float*)d_in[2];
    const float* wqkv  = (const float*)d_in[3];
    const float* wout  = (const float*)d_in[4];
    float* out = (float*)d_out;

    cudaFuncSetAttribute(gemm_mma<0>, cudaFuncAttributeMaxDynamicSharedMemorySize, 3 * GSTAGE);
    cudaFuncSetAttribute(gemm_mma<1>, cudaFuncAttributeMaxDynamicSharedMemorySize, 3 * GSTAGE);
    cudaFuncSetAttribute(attn_kernel, cudaFuncAttributeMaxDynamicSharedMemorySize, 3 * AST);

    prep_kernel<<<TOKENS + CONV0_BLKS + CONV1_BLKS, 256>>>(x, gamma, beta, wqkv, wout);
    gemm_mma<0><<<dim3(QKV_N / 128, TOKENS / 128), 128, 3 * GSTAGE>>>(nullptr);
    attn_kernel<<<dim3(NSEQ / 128, BH_N), 128, 3 * AST>>>();
    gemm_mma<1><<<dim3(DIM / 128, TOKENS / 128), 128, 3 * GSTAGE>>>(out);
}